// round 4
// baseline (speedup 1.0000x reference)
#include <cuda_runtime.h>
#include <math.h>

// MaskedLightAdaIN: x [16,64,256,256] f32, mask [16,1,256,256] f32
// out = where(mask>=0.5, x, (x - mu_bg)/(sig_bg+eps)*sig_fg + mu_fg)
// stats are masked mean / unbiased std per (B,C).

#define NB   16
#define NC   64
#define NBC  (NB * NC)          // 1024 planes
#define HW   65536              // 256*256
#define HW4  16384              // HW / 4
#define EPSV 1e-8f

// per-(b,c) stats: x=mu_fg, y=sig_fg, z=mu_bg, w=sig_bg
__device__ float4 g_stats[NBC];

// ---------------------------------------------------------------------------
// Kernel 1: one block per (b,c) plane. Single read of the plane, accumulating
// (sum, sumsq, sum_fg, sumsq_fg, n_fg); bg stats derived as (all - fg).
// ---------------------------------------------------------------------------
__global__ void __launch_bounds__(512) stats_kernel(const float* __restrict__ x,
                                                    const float* __restrict__ mask)
{
    const int bc = blockIdx.x;           // 0..1023
    const int b  = bc >> 6;              // batch

    const float4* __restrict__ xp = reinterpret_cast<const float4*>(x)    + (size_t)bc * HW4;
    const float4* __restrict__ mp = reinterpret_cast<const float4*>(mask) + (size_t)b  * HW4;

    float s_all = 0.f, q_all = 0.f, s_fg = 0.f, q_fg = 0.f, n_fg = 0.f;

    #pragma unroll 4
    for (int i = threadIdx.x; i < HW4; i += 512) {
        float4 xv = xp[i];
        float4 mv = mp[i];

        float x0 = xv.x, x1 = xv.y, x2 = xv.z, x3 = xv.w;
        float w0 = (mv.x >= 0.5f) ? 1.f : 0.f;
        float w1 = (mv.y >= 0.5f) ? 1.f : 0.f;
        float w2 = (mv.z >= 0.5f) ? 1.f : 0.f;
        float w3 = (mv.w >= 0.5f) ? 1.f : 0.f;

        s_all += x0 + x1 + x2 + x3;
        q_all += x0*x0 + x1*x1 + x2*x2 + x3*x3;
        s_fg  += x0*w0 + x1*w1 + x2*w2 + x3*w3;
        q_fg  += x0*x0*w0 + x1*x1*w1 + x2*x2*w2 + x3*x3*w3;
        n_fg  += w0 + w1 + w2 + w3;
    }

    // warp reduce (5 values)
    #pragma unroll
    for (int o = 16; o > 0; o >>= 1) {
        s_all += __shfl_xor_sync(0xffffffffu, s_all, o);
        q_all += __shfl_xor_sync(0xffffffffu, q_all, o);
        s_fg  += __shfl_xor_sync(0xffffffffu, s_fg,  o);
        q_fg  += __shfl_xor_sync(0xffffffffu, q_fg,  o);
        n_fg  += __shfl_xor_sync(0xffffffffu, n_fg,  o);
    }

    __shared__ float red[16][5];
    const int warp = threadIdx.x >> 5;
    const int lane = threadIdx.x & 31;
    if (lane == 0) {
        red[warp][0] = s_all; red[warp][1] = q_all;
        red[warp][2] = s_fg;  red[warp][3] = q_fg;
        red[warp][4] = n_fg;
    }
    __syncthreads();

    if (warp == 0) {
        float v0 = (lane < 16) ? red[lane][0] : 0.f;
        float v1 = (lane < 16) ? red[lane][1] : 0.f;
        float v2 = (lane < 16) ? red[lane][2] : 0.f;
        float v3 = (lane < 16) ? red[lane][3] : 0.f;
        float v4 = (lane < 16) ? red[lane][4] : 0.f;
        #pragma unroll
        for (int o = 8; o > 0; o >>= 1) {
            v0 += __shfl_xor_sync(0xffffffffu, v0, o);
            v1 += __shfl_xor_sync(0xffffffffu, v1, o);
            v2 += __shfl_xor_sync(0xffffffffu, v2, o);
            v3 += __shfl_xor_sync(0xffffffffu, v3, o);
            v4 += __shfl_xor_sync(0xffffffffu, v4, o);
        }
        if (lane == 0) {
            const float n_total = (float)HW;
            float nf = v4;
            float nb = n_total - nf;

            float s_f = v2,        q_f = v3;
            float s_b = v0 - v2,   q_b = v1 - v3;

            float mu_f  = s_f / nf;
            float var_f = fmaxf(q_f - s_f * mu_f, 0.f) / (nf - 1.f);
            float sig_f = sqrtf(var_f);

            float mu_b  = s_b / nb;
            float var_b = fmaxf(q_b - s_b * mu_b, 0.f) / (nb - 1.f);
            float sig_b = sqrtf(var_b);

            g_stats[bc] = make_float4(mu_f, sig_f, mu_b, sig_b);
        }
    }
}

// ---------------------------------------------------------------------------
// Kernel 2: elementwise apply, float4-vectorized. One float4 per thread.
// harmonized = x*scale + bias; out = fg ? x : harmonized.
// ---------------------------------------------------------------------------
__global__ void __launch_bounds__(256) apply_kernel(const float* __restrict__ x,
                                                    const float* __restrict__ mask,
                                                    float* __restrict__ out)
{
    const size_t i = (size_t)blockIdx.x * 256 + threadIdx.x;   // float4 index
    const int bc  = (int)(i >> 14);       // /HW4
    const int b   = bc >> 6;
    const int hw4 = (int)(i & (HW4 - 1));

    float4 xv = reinterpret_cast<const float4*>(x)[i];
    float4 mv = reinterpret_cast<const float4*>(mask)[(size_t)b * HW4 + hw4];
    float4 st = g_stats[bc];   // mu_fg, sig_fg, mu_bg, sig_bg

    const float scale = st.y / (st.w + EPSV);
    const float bias  = st.x - st.z * scale;

    float4 ov;
    ov.x = (mv.x >= 0.5f) ? xv.x : fmaf(xv.x, scale, bias);
    ov.y = (mv.y >= 0.5f) ? xv.y : fmaf(xv.y, scale, bias);
    ov.z = (mv.z >= 0.5f) ? xv.z : fmaf(xv.z, scale, bias);
    ov.w = (mv.w >= 0.5f) ? xv.w : fmaf(xv.w, scale, bias);

    reinterpret_cast<float4*>(out)[i] = ov;
}

extern "C" void kernel_launch(void* const* d_in, const int* in_sizes, int n_in,
                              void* d_out, int out_size)
{
    const float* x    = (const float*)d_in[0];   // 16*64*256*256
    const float* mask = (const float*)d_in[1];   // 16*1*256*256
    float* out        = (float*)d_out;

    stats_kernel<<<NBC, 512>>>(x, mask);

    const int total4 = NBC * HW4;                // 16,777,216 * ... = 16777216? no: 1024*16384 = 16,777,216
    const int blocks = total4 / 256;             // 65536 blocks
    apply_kernel<<<blocks, 256>>>(x, mask, out);
}